// round 14
// baseline (speedup 1.0000x reference)
#include <cuda_runtime.h>
#include <cuda_bf16.h>
#include <cstdint>

// Problem dims
#define MDIM 256
#define TDIM 512
#define NXDIM 256
#define UDIM 256

// Scratch for x-projections: 3 matrices x [T][M][U] fp32 = 402 MB.
#define XP_STRIDE (33554432ULL) // 512*256*256
__device__ float g_xp[3ULL * XP_STRIDE];

// ---------------- packed f32x2 helpers ----------------
#define FFMA2(c_, a_, b_) \
    asm volatile("fma.rn.f32x2 %0, %1, %2, %0;" : "+l"(c_) : "l"(a_), "l"(b_))
#define ADD2(o_, a_, b_) \
    asm("add.rn.f32x2 %0, %1, %2;" : "=l"(o_) : "l"(a_), "l"(b_))

__device__ __forceinline__ unsigned long long dup2(float a) {
    unsigned long long r;
    asm("mov.b64 %0, {%1, %1};" : "=l"(r) : "f"(a));
    return r;
}
__device__ __forceinline__ unsigned long long pack2(float lo, float hi) {
    unsigned long long r;
    asm("mov.b64 %0, {%1, %2};" : "=l"(r) : "f"(lo), "f"(hi));
    return r;
}
__device__ __forceinline__ void unpack2(float& lo, float& hi, unsigned long long v) {
    asm("mov.b64 {%0, %1}, %2;" : "=f"(lo), "=f"(hi) : "l"(v));
}

// ---------------- cluster / DSMEM helpers ----------------
__device__ __forceinline__ uint32_t smem_u32(const void* p) {
    uint32_t a;
    asm("{ .reg .u64 t; cvta.to.shared.u64 t, %1; cvt.u32.u64 %0, t; }"
        : "=r"(a) : "l"(p));
    return a;
}
__device__ __forceinline__ uint32_t mapa_rank(uint32_t addr, uint32_t rank) {
    uint32_t r;
    asm("mapa.shared::cluster.u32 %0, %1, %2;" : "=r"(r) : "r"(addr), "r"(rank));
    return r;
}
__device__ __forceinline__ void st_cluster_u64(uint32_t addr, unsigned long long v) {
    asm volatile("st.shared::cluster.u64 [%0], %1;" :: "r"(addr), "l"(v) : "memory");
}
__device__ __forceinline__ uint32_t ctarank() {
    uint32_t r; asm("mov.u32 %0, %%cluster_ctarank;" : "=r"(r)); return r;
}
#define CLUSTER_SYNC_() do { \
    asm volatile("barrier.cluster.arrive.aligned;" ::: "memory"); \
    asm volatile("barrier.cluster.wait.aligned;" ::: "memory"); } while (0)

__device__ __forceinline__ void mbar_init(uint32_t bar, uint32_t cnt) {
    asm volatile("mbarrier.init.shared.b64 [%0], %1;" :: "r"(bar), "r"(cnt) : "memory");
}
__device__ __forceinline__ void mbar_arrive_rank(uint32_t local_bar, uint32_t rank) {
    uint32_t remote = mapa_rank(local_bar, rank);
    asm volatile("mbarrier.arrive.release.cluster.shared::cluster.b64 _, [%0];"
                 :: "r"(remote) : "memory");
}
__device__ __forceinline__ void mbar_wait_parity(uint32_t bar, uint32_t parity) {
    uint32_t done;
    asm volatile(
        "{\n\t.reg .pred p;\n\t"
        "mbarrier.try_wait.parity.acquire.cluster.shared::cta.b64 p, [%1], %2;\n\t"
        "selp.b32 %0, 1, 0, p;\n\t}"
        : "=r"(done) : "r"(bar), "r"(parity) : "memory");
    if (!done) {
        asm volatile(
            "{\n\t.reg .pred P1;\n\t"
            "WLOOP_%=:\n\t"
            "mbarrier.try_wait.parity.acquire.cluster.shared::cta.b64 P1, [%0], %1, 0x989680;\n\t"
            "@P1 bra.uni WDONE_%=;\n\t"
            "bra.uni WLOOP_%=;\n\t"
            "WDONE_%=:\n\t}"
            :: "r"(bar), "r"(parity) : "memory");
    }
}

// 64-bit xor shfl (2x SHFL.b32)
__device__ __forceinline__ unsigned long long shfl64(unsigned long long v, int m) {
    return __shfl_xor_sync(0xffffffffu, v, m);
}

// Butterfly reduction step: v[0..2N) -> v[0..N).
template<int N>
__device__ __forceinline__ void redstep(unsigned long long* v, bool sel, int m) {
    #pragma unroll
    for (int i = 0; i < N; i++) {
        unsigned long long mine = sel ? v[i + N] : v[i];
        unsigned long long send = sel ? v[i] : v[i + N];
        unsigned long long r = shfl64(send, m);
        ADD2(v[i], mine, r);
    }
}

// =====================================================================
// Phase 1: x projections (unchanged — validated, ~1.0 ms, near fp32 peak).
// =====================================================================
__global__ __launch_bounds__(256, 1)
void xproj_kernel(const float* __restrict__ x,
                  const float* __restrict__ w_u,
                  const float* __restrict__ w_r,
                  const float* __restrict__ w_c)
{
    const float* __restrict__ w =
        (blockIdx.z == 0) ? w_u : ((blockIdx.z == 1) ? w_r : w_c);
    float* __restrict__ outp = g_xp + (size_t)blockIdx.z * XP_STRIDE;

    const int tid = threadIdx.x;
    const int g0  = blockIdx.x * 128;
    const int t   = g0 >> 8;
    const int m0  = g0 & 255;
    const int n0  = blockIdx.y * 128;

    __shared__ float As[16][132];
    __shared__ float Bs[16][128];

    const int tx = tid & 15;
    const int ty = tid >> 4;

    unsigned long long acc[8][4];
    #pragma unroll
    for (int i = 0; i < 8; i++)
        #pragma unroll
        for (int j = 0; j < 4; j++) acc[i][j] = 0ULL;

    for (int kk = 0; kk < NXDIM; kk += 16) {
        #pragma unroll
        for (int l = 0; l < 2; l++) {
            int f  = tid + l * 256;
            int i  = f >> 2;
            int kv = (f & 3) * 4;
            const float4 v = *(const float4*)(x +
                ((size_t)(m0 + i) * TDIM + t) * NXDIM + kk + kv);
            As[kv + 0][i] = v.x;
            As[kv + 1][i] = v.y;
            As[kv + 2][i] = v.z;
            As[kv + 3][i] = v.w;
        }
        #pragma unroll
        for (int l = 0; l < 2; l++) {
            int f  = tid + l * 256;
            int k  = f >> 5;
            int nn = (f & 31) * 4;
            *(float4*)&Bs[k][nn] =
                *(const float4*)(w + (size_t)(kk + k) * UDIM + n0 + nn);
        }
        __syncthreads();

        #pragma unroll
        for (int k = 0; k < 16; k++) {
            float4 a0v = *(const float4*)&As[k][ty * 8];
            float4 a1v = *(const float4*)&As[k][ty * 8 + 4];
            const unsigned long long* bp =
                (const unsigned long long*)&Bs[k][tx * 8];
            unsigned long long b0 = bp[0], b1 = bp[1], b2 = bp[2], b3 = bp[3];
            float av[8] = {a0v.x, a0v.y, a0v.z, a0v.w,
                           a1v.x, a1v.y, a1v.z, a1v.w};
            #pragma unroll
            for (int i = 0; i < 8; i++) {
                unsigned long long ad = dup2(av[i]);
                FFMA2(acc[i][0], ad, b0);
                FFMA2(acc[i][1], ad, b1);
                FFMA2(acc[i][2], ad, b2);
                FFMA2(acc[i][3], ad, b3);
            }
        }
        __syncthreads();
    }

    #pragma unroll
    for (int i = 0; i < 8; i++) {
        int g = g0 + ty * 8 + i;
        float o[8];
        unpack2(o[0], o[1], acc[i][0]);
        unpack2(o[2], o[3], acc[i][1]);
        unpack2(o[4], o[5], acc[i][2]);
        unpack2(o[6], o[7], acc[i][3]);
        float* op = outp + (size_t)g * UDIM + n0 + tx * 8;
        *(float4*)(op)     = make_float4(o[0], o[1], o[2], o[3]);
        *(float4*)(op + 4) = make_float4(o[4], o[5], o[6], o[7]);
    }
}

// =====================================================================
// Phase 2: GRU scan — 32 clusters x 4 CTAs, 256 threads/CTA.
//   Data layout identical to R11/R12 (validated).  NEW in this round:
//   explicit 2-stage register pipeline in both GEMV loops (prefetch
//   iteration i+1's smem operands before issuing iteration i's FFMA2s)
//   so LDS flight overlaps FMA issue; j order = (jloc+i)&15 keeps the
//   local-first / wait-before-first-remote-prefetch structure (wait
//   sits at i==3, right before prefetching jseq(4) = first remote).
//   tanh via sigmoid identity (__expf) to shorten the serial c-update.
// =====================================================================
#define NSTW 68
#define NSTC 76
#define OWU 8
#define OWR (OWU + 256 * NSTW)        // 17416
#define OWC (OWR + 256 * NSTW)        // 34824
#define SMF (OWC + 256 * NSTC)        // 54280 floats
#define SMB (SMF * 4)                 // 217120 bytes

__device__ __forceinline__ float sigmoid_f(float z) {
    return 1.0f / (1.0f + __expf(-z));
}
__device__ __forceinline__ float tanh_f(float z) {
    return fmaf(2.0f, sigmoid_f(2.0f * z), -1.0f);
}

__global__ __launch_bounds__(256, 1) __cluster_dims__(4, 1, 1)
void gru_scan7(const float* __restrict__ wuc,
               const float* __restrict__ wrc,
               const float* __restrict__ wcc,
               const float* __restrict__ bu,
               const float* __restrict__ br,
               const float* __restrict__ bc,
               const float* __restrict__ a0,
               float* __restrict__ out)
{
    extern __shared__ float sm[];
    float* wu_s = sm + OWU;
    float* wr_s = sm + OWR;
    float* wc_s = sm + OWC;

    const int tid = threadIdx.x;
    const uint32_t rank = ctarank();
    const int n0 = (int)rank * 64;
    const int r0 = (blockIdx.x >> 2) * 8;

    const int ks    = tid & 15;
    const int ng    = tid >> 4;
    const int nbase = ng * 4;
    const bool b3 = (ks & 8) != 0, b2 = (ks & 4) != 0,
               b1 = (ks & 2) != 0, b0 = (ks & 1) != 0;
    const int p     = ks & 3;                  // owned row-pair index
    const int col_g = n0 + nbase + (ks >> 2);  // owned unit
    const int m_own = r0 + 2 * p;              // owned rows m_own, m_own+1
    const int jloc  = (int)rank * 4;           // local j-block start

    const uint32_t barH = smem_u32(sm);
    const uint32_t barC = barH + 8;
    if (tid == 0) { mbar_init(barH, 4); mbar_init(barC, 4); }

    // ---- weights k-major into smem (each word written once) ----
    for (int i = tid; i < 64 * 256; i += 256) {
        int k = i >> 6, n = i & 63;
        wu_s[k * NSTW + n] = wuc[k * UDIM + n0 + n];
        wr_s[k * NSTW + n] = wrc[k * UDIM + n0 + n];
        wc_s[k * NSTC + n] = wcc[k * UDIM + n0 + n];
    }
    // ---- c init into wc pads: c[u][r] at wc_s[u*76 + 64 + r] ----
    for (int i = tid; i < 256 * 8; i += 256) {
        int u = i >> 3, r = i & 7;
        wc_s[u * NSTC + 64 + r] = a0[(size_t)(r0 + r) * UDIM + u];
    }
    float cme0 = a0[(size_t)(m_own + 0) * UDIM + col_g];
    float cme1 = a0[(size_t)(m_own + 1) * UDIM + col_g];
    const float bun = bu[col_g], brn = br[col_g], bcn = bc[col_g];

    // ---- DSMEM broadcast targets (one u64 per thread per gate) ----
    uint32_t hbase = (p < 2)
        ? smem_u32(wu_s + col_g * NSTW + 64 + 2 * p)
        : smem_u32(wr_s + col_g * NSTW + 64 + 2 * (p - 2));
    uint32_t cbase = smem_u32(wc_s + col_g * NSTC + 64 + 2 * p);
    uint32_t hdst[4], cdst[4];
    #pragma unroll
    for (int d = 0; d < 4; d++) {
        hdst[d] = mapa_rank(hbase, d);
        cdst[d] = mapa_rank(cbase, d);
    }

    __syncthreads();
    CLUSTER_SYNC_();

    const float* __restrict__ xu = g_xp;
    const float* __restrict__ xr = g_xp + XP_STRIDE;
    const float* __restrict__ xc = g_xp + 2ULL * XP_STRIDE;

    const float* wup = wu_s + ks * NSTW + nbase;
    const float* wrp = wr_s + ks * NSTW + nbase;
    const float* wcp = wc_s + ks * NSTC + nbase;
    const float* cpp = wc_s + ks * NSTC + 64;   // c rows
    const float* hup = wu_s + ks * NSTW + 64;   // h rows 0..3
    const float* hrp = wr_s + ks * NSTW + 64;   // h rows 4..7

    unsigned long long aU[16], aR[16], aC[16];

    for (int t = 0; t < TDIM; t++) {
        const uint32_t ph = (uint32_t)(t & 1);

        // prefetch x-projection terms for owned (col, 2 rows)
        const size_t xo = (size_t)t * (MDIM * UDIM) + (size_t)m_own * UDIM + col_g;
        const float xu0 = __ldg(xu + xo), xu1 = __ldg(xu + xo + UDIM);
        const float xr0 = __ldg(xr + xo), xr1 = __ldg(xr + xo + UDIM);
        const float xc0 = __ldg(xc + xo), xc1 = __ldg(xc + xo + UDIM);

        // ================= phase A: pre_u, pre_r (pipelined) =============
        #pragma unroll
        for (int i = 0; i < 16; i++) { aU[i] = 0ULL; aR[i] = 0ULL; }

        {
            // stage-0 prefetch: j = jseq(0) = jloc (local)
            float4 wu_n = *(const float4*)(wup + jloc * (16 * NSTW));
            float4 wr_n = *(const float4*)(wrp + jloc * (16 * NSTW));
            ulonglong2 cA_n = *(const ulonglong2*)(cpp + jloc * (16 * NSTC));
            ulonglong2 cB_n = *(const ulonglong2*)(cpp + jloc * (16 * NSTC) + 4);

            #pragma unroll
            for (int i = 0; i < 16; i++) {
                const float4 wu_c = wu_n, wr_c = wr_n;
                const ulonglong2 cA_c = cA_n, cB_c = cB_n;

                if (i == 3 && t > 0)   // before first REMOTE prefetch
                    mbar_wait_parity(barC, (uint32_t)((t - 1) & 1));
                if (i < 15) {
                    const int jn = (jloc + i + 1) & 15;
                    wu_n = *(const float4*)(wup + jn * (16 * NSTW));
                    wr_n = *(const float4*)(wrp + jn * (16 * NSTW));
                    cA_n = *(const ulonglong2*)(cpp + jn * (16 * NSTC));
                    cB_n = *(const ulonglong2*)(cpp + jn * (16 * NSTC) + 4);
                }

                const unsigned long long c2[4] = {cA_c.x, cA_c.y, cB_c.x, cB_c.y};
                const float wuf[4] = {wu_c.x, wu_c.y, wu_c.z, wu_c.w};
                const float wrf[4] = {wr_c.x, wr_c.y, wr_c.z, wr_c.w};
                #pragma unroll
                for (int c = 0; c < 4; c++) {
                    const unsigned long long du = dup2(wuf[c]);
                    const unsigned long long dr = dup2(wrf[c]);
                    #pragma unroll
                    for (int q = 0; q < 4; q++) {
                        FFMA2(aU[c * 4 + q], c2[q], du);
                        FFMA2(aR[c * 4 + q], c2[q], dr);
                    }
                }
            }
        }

        // 16-way k-reduce: cols (b3,b2) then row-pairs (b1,b0)
        redstep<8>(aU, b3, 8);  redstep<8>(aR, b3, 8);
        redstep<4>(aU, b2, 4);  redstep<4>(aR, b2, 4);
        redstep<2>(aU, b1, 2);  redstep<2>(aR, b1, 2);
        redstep<1>(aU, b0, 1);  redstep<1>(aR, b0, 1);

        float pu0, pu1, pr0, pr1;
        unpack2(pu0, pu1, aU[0]);
        unpack2(pr0, pr1, aR[0]);

        const float h0 = sigmoid_f(pr0 + xr0 + brn) * cme0;
        const float h1 = sigmoid_f(pr1 + xr1 + brn) * cme1;
        // broadcast h immediately (gu computes under the store flight)
        {
            const unsigned long long h01 = pack2(h0, h1);
            #pragma unroll
            for (int d = 0; d < 4; d++) st_cluster_u64(hdst[d], h01);
        }
        const float gu0 = sigmoid_f(pu0 + xu0 + bun);
        const float gu1 = sigmoid_f(pu1 + xu1 + bun);

        __syncthreads();                       // local h visible CTA-wide
        if (tid < 4) mbar_arrive_rank(barH, (uint32_t)tid);

        // ================= phase B: pre_c (pipelined) =================
        #pragma unroll
        for (int i = 0; i < 16; i++) aC[i] = 0ULL;

        {
            float4 wc_n = *(const float4*)(wcp + jloc * (16 * NSTC));
            ulonglong2 hA_n = *(const ulonglong2*)(hup + jloc * (16 * NSTW));
            ulonglong2 hB_n = *(const ulonglong2*)(hrp + jloc * (16 * NSTW));

            #pragma unroll
            for (int i = 0; i < 16; i++) {
                const float4 wc_c = wc_n;
                const ulonglong2 hA_c = hA_n, hB_c = hB_n;

                if (i == 3)            // before first REMOTE prefetch
                    mbar_wait_parity(barH, ph);
                if (i < 15) {
                    const int jn = (jloc + i + 1) & 15;
                    wc_n = *(const float4*)(wcp + jn * (16 * NSTC));
                    hA_n = *(const ulonglong2*)(hup + jn * (16 * NSTW));
                    hB_n = *(const ulonglong2*)(hrp + jn * (16 * NSTW));
                }

                const unsigned long long h2[4] = {hA_c.x, hA_c.y, hB_c.x, hB_c.y};
                const float wcf[4] = {wc_c.x, wc_c.y, wc_c.z, wc_c.w};
                #pragma unroll
                for (int c = 0; c < 4; c++) {
                    const unsigned long long dc = dup2(wcf[c]);
                    #pragma unroll
                    for (int q = 0; q < 4; q++)
                        FFMA2(aC[c * 4 + q], h2[q], dc);
                }
            }
        }

        redstep<8>(aC, b3, 8);
        redstep<4>(aC, b2, 4);
        redstep<2>(aC, b1, 2);
        redstep<1>(aC, b0, 1);

        float pc0, pc1;
        unpack2(pc0, pc1, aC[0]);

        const float cand0 = tanh_f(pc0 + xc0 + bcn);
        const float cand1 = tanh_f(pc1 + xc1 + bcn);
        cme0 = fmaf(gu0, cand0 - cme0, cme0);
        cme1 = fmaf(gu1, cand1 - cme1, cme1);

        // broadcast c_new; arrive barC (wait happens in next step's phase A)
        {
            const unsigned long long c01 = pack2(cme0, cme1);
            #pragma unroll
            for (int d = 0; d < 4; d++) st_cluster_u64(cdst[d], c01);
        }
        __syncthreads();                       // local c visible CTA-wide
        if (tid < 4) mbar_arrive_rank(barC, (uint32_t)tid);
    }

    out[(size_t)(m_own + 0) * UDIM + col_g] = cme0;
    out[(size_t)(m_own + 1) * UDIM + col_g] = cme1;

    CLUSTER_SYNC_();   // no CTA exits while peers' DSMEM stores in flight
}

// =====================================================================
// Launch
// Inputs (metadata order):
//  0:x [256,512,256]  1:a0 [256,256]
//  2:wcx 3:wcc 4:bc   5:wux 6:wuc 7:bu   8:wrx 9:wrc 10:br
// =====================================================================
extern "C" void kernel_launch(void* const* d_in, const int* in_sizes, int n_in,
                              void* d_out, int out_size)
{
    const float* x   = (const float*)d_in[0];
    const float* a0  = (const float*)d_in[1];
    const float* wcx = (const float*)d_in[2];
    const float* wcc = (const float*)d_in[3];
    const float* bc  = (const float*)d_in[4];
    const float* wux = (const float*)d_in[5];
    const float* wuc = (const float*)d_in[6];
    const float* bu  = (const float*)d_in[7];
    const float* wrx = (const float*)d_in[8];
    const float* wrc = (const float*)d_in[9];
    const float* br  = (const float*)d_in[10];
    float* out = (float*)d_out;

    cudaFuncSetAttribute(gru_scan7,
                         cudaFuncAttributeMaxDynamicSharedMemorySize, SMB);

    // Phase 1: x projections (z=0 -> wux, z=1 -> wrx, z=2 -> wcx)
    dim3 g1((MDIM * TDIM) / 128, UDIM / 128, 3);
    xproj_kernel<<<g1, 256>>>(x, wux, wrx, wcx);

    // Phase 2: sequential scan — 32 clusters x 4 CTAs, 256 thr
    gru_scan7<<<128, 256, SMB>>>(wuc, wrc, wcc, bu, br, bc, a0, out);
}

// round 15
// speedup vs baseline: 1.0653x; 1.0653x over previous
#include <cuda_runtime.h>
#include <cuda_bf16.h>
#include <cstdint>

// Problem dims
#define MDIM 256
#define TDIM 512
#define NXDIM 256
#define UDIM 256

// Scratch for x-projections: 3 matrices x [T][M][U] fp32 = 402 MB.
#define XP_STRIDE (33554432ULL) // 512*256*256
__device__ float g_xp[3ULL * XP_STRIDE];

// Per-timestep completion counters for producer(xproj)/consumer(scan).
// 24 xproj CTAs contribute to each t (4 x-blocks * 2 y * 3 z).
#define XP_CTAS_PER_T 24
__device__ int g_cnt[TDIM];

// ---------------- packed f32x2 helpers ----------------
#define FFMA2(c_, a_, b_) \
    asm volatile("fma.rn.f32x2 %0, %1, %2, %0;" : "+l"(c_) : "l"(a_), "l"(b_))
#define ADD2(o_, a_, b_) \
    asm("add.rn.f32x2 %0, %1, %2;" : "=l"(o_) : "l"(a_), "l"(b_))

__device__ __forceinline__ unsigned long long dup2(float a) {
    unsigned long long r;
    asm("mov.b64 %0, {%1, %1};" : "=l"(r) : "f"(a));
    return r;
}
__device__ __forceinline__ unsigned long long pack2(float lo, float hi) {
    unsigned long long r;
    asm("mov.b64 %0, {%1, %2};" : "=l"(r) : "f"(lo), "f"(hi));
    return r;
}
__device__ __forceinline__ void unpack2(float& lo, float& hi, unsigned long long v) {
    asm("mov.b64 {%0, %1}, %2;" : "=f"(lo), "=f"(hi) : "l"(v));
}

// ---------------- cluster / DSMEM helpers ----------------
__device__ __forceinline__ uint32_t smem_u32(const void* p) {
    uint32_t a;
    asm("{ .reg .u64 t; cvta.to.shared.u64 t, %1; cvt.u32.u64 %0, t; }"
        : "=r"(a) : "l"(p));
    return a;
}
__device__ __forceinline__ uint32_t mapa_rank(uint32_t addr, uint32_t rank) {
    uint32_t r;
    asm("mapa.shared::cluster.u32 %0, %1, %2;" : "=r"(r) : "r"(addr), "r"(rank));
    return r;
}
__device__ __forceinline__ void st_cluster_u64(uint32_t addr, unsigned long long v) {
    asm volatile("st.shared::cluster.u64 [%0], %1;" :: "r"(addr), "l"(v) : "memory");
}
__device__ __forceinline__ uint32_t ctarank() {
    uint32_t r; asm("mov.u32 %0, %%cluster_ctarank;" : "=r"(r)); return r;
}
#define CLUSTER_SYNC_() do { \
    asm volatile("barrier.cluster.arrive.aligned;" ::: "memory"); \
    asm volatile("barrier.cluster.wait.aligned;" ::: "memory"); } while (0)

__device__ __forceinline__ void mbar_init(uint32_t bar, uint32_t cnt) {
    asm volatile("mbarrier.init.shared.b64 [%0], %1;" :: "r"(bar), "r"(cnt) : "memory");
}
__device__ __forceinline__ void mbar_arrive_rank(uint32_t local_bar, uint32_t rank) {
    uint32_t remote = mapa_rank(local_bar, rank);
    asm volatile("mbarrier.arrive.release.cluster.shared::cluster.b64 _, [%0];"
                 :: "r"(remote) : "memory");
}
__device__ __forceinline__ void mbar_wait_parity(uint32_t bar, uint32_t parity) {
    uint32_t done;
    asm volatile(
        "{\n\t.reg .pred p;\n\t"
        "mbarrier.try_wait.parity.acquire.cluster.shared::cta.b64 p, [%1], %2;\n\t"
        "selp.b32 %0, 1, 0, p;\n\t}"
        : "=r"(done) : "r"(bar), "r"(parity) : "memory");
    if (!done) {
        asm volatile(
            "{\n\t.reg .pred P1;\n\t"
            "WLOOP_%=:\n\t"
            "mbarrier.try_wait.parity.acquire.cluster.shared::cta.b64 P1, [%0], %1, 0x989680;\n\t"
            "@P1 bra.uni WDONE_%=;\n\t"
            "bra.uni WLOOP_%=;\n\t"
            "WDONE_%=:\n\t}"
            :: "r"(bar), "r"(parity) : "memory");
    }
}

// 64-bit xor shfl (2x SHFL.b32)
__device__ __forceinline__ unsigned long long shfl64(unsigned long long v, int m) {
    return __shfl_xor_sync(0xffffffffu, v, m);
}

// Butterfly reduction step: v[0..2N) -> v[0..N).
template<int N>
__device__ __forceinline__ void redstep(unsigned long long* v, bool sel, int m) {
    #pragma unroll
    for (int i = 0; i < N; i++) {
        unsigned long long mine = sel ? v[i + N] : v[i];
        unsigned long long send = sel ? v[i] : v[i + N];
        unsigned long long r = shfl64(send, m);
        ADD2(v[i], mine, r);
    }
}

// L2-coherent load for the flag poll (bypasses L1).
__device__ __forceinline__ int ld_cg(const int* p) {
    int v;
    asm volatile("ld.global.cg.b32 %0, [%1];" : "=r"(v) : "l"(p));
    return v;
}
__device__ __forceinline__ void wait_ready(int t) {
    while (ld_cg(&g_cnt[t]) < XP_CTAS_PER_T) { }
    __threadfence();   // order the subsequent xp reads after the flag
}

// =====================================================================
// Phase 1: x projections — co-residency build: BM=64, BN=128, BK=8,
//   128 threads, <=128 regs, 6.3 KB smem, so one xproj CTA fits on an
//   SM alongside a resident scan CTA (217 KB smem, 256 thr, 152 regs).
//   grid = (2048, 2, 3); 24 CTAs per timestep t; each bumps g_cnt[t].
// =====================================================================
__global__ __launch_bounds__(128, 4)
void xproj_kernel(const float* __restrict__ x,
                  const float* __restrict__ w_u,
                  const float* __restrict__ w_r,
                  const float* __restrict__ w_c)
{
    const float* __restrict__ w =
        (blockIdx.z == 0) ? w_u : ((blockIdx.z == 1) ? w_r : w_c);
    float* __restrict__ outp = g_xp + (size_t)blockIdx.z * XP_STRIDE;

    const int tid = threadIdx.x;
    const int g0  = blockIdx.x * 64;
    const int t   = g0 >> 8;
    const int m0  = g0 & 255;
    const int n0  = blockIdx.y * 128;

    __shared__ float As[8][68];    // [k][m]
    __shared__ float Bs[8][128];   // [k][n]

    const int tx = tid & 15;       // 8 cols each
    const int ty = tid >> 4;       // 8 rows each

    unsigned long long acc[8][4];
    #pragma unroll
    for (int i = 0; i < 8; i++)
        #pragma unroll
        for (int j = 0; j < 4; j++) acc[i][j] = 0ULL;

    for (int kk = 0; kk < NXDIM; kk += 8) {
        // A tile: 64 rows x 8 k, transposed into As[k][m]
        {
            int i  = tid >> 1;
            int kv = (tid & 1) * 4;
            const float4 v = *(const float4*)(x +
                ((size_t)(m0 + i) * TDIM + t) * NXDIM + kk + kv);
            As[kv + 0][i] = v.x;
            As[kv + 1][i] = v.y;
            As[kv + 2][i] = v.z;
            As[kv + 3][i] = v.w;
        }
        // B tile: 8 k x 128 n
        #pragma unroll
        for (int l = 0; l < 2; l++) {
            int f  = tid + l * 128;
            int k  = f >> 5;
            int nn = (f & 31) * 4;
            *(float4*)&Bs[k][nn] =
                *(const float4*)(w + (size_t)(kk + k) * UDIM + n0 + nn);
        }
        __syncthreads();

        #pragma unroll
        for (int k = 0; k < 8; k++) {
            float4 a0v = *(const float4*)&As[k][ty * 8];
            float4 a1v = *(const float4*)&As[k][ty * 8 + 4];
            const unsigned long long* bp =
                (const unsigned long long*)&Bs[k][tx * 8];
            unsigned long long b0 = bp[0], b1 = bp[1], b2 = bp[2], b3 = bp[3];
            float av[8] = {a0v.x, a0v.y, a0v.z, a0v.w,
                           a1v.x, a1v.y, a1v.z, a1v.w};
            #pragma unroll
            for (int i = 0; i < 8; i++) {
                unsigned long long ad = dup2(av[i]);
                FFMA2(acc[i][0], ad, b0);
                FFMA2(acc[i][1], ad, b1);
                FFMA2(acc[i][2], ad, b2);
                FFMA2(acc[i][3], ad, b3);
            }
        }
        __syncthreads();
    }

    #pragma unroll
    for (int i = 0; i < 8; i++) {
        int g = g0 + ty * 8 + i;
        float o[8];
        unpack2(o[0], o[1], acc[i][0]);
        unpack2(o[2], o[3], acc[i][1]);
        unpack2(o[4], o[5], acc[i][2]);
        unpack2(o[6], o[7], acc[i][3]);
        float* op = outp + (size_t)g * UDIM + n0 + tx * 8;
        *(float4*)(op)     = make_float4(o[0], o[1], o[2], o[3]);
        *(float4*)(op + 4) = make_float4(o[4], o[5], o[6], o[7]);
    }

    __syncthreads();
    if (tid == 0) {
        __threadfence();
        atomicAdd(&g_cnt[t], 1);
    }
}

// =====================================================================
// Phase 2: GRU scan — R12 structure (best validated: 1.995 ms scan),
//   plus: (a) cudaTriggerProgrammaticLaunchCompletion after setup so
//   the PDL-launched xproj can co-schedule, (b) per-step flag polls
//   (poll for t+1 placed in the phase A->B slack), (c) tanh via
//   sigmoid identity.
// =====================================================================
#define NSTW 68
#define NSTC 76
#define OWU 8
#define OWR (OWU + 256 * NSTW)        // 17416
#define OWC (OWR + 256 * NSTW)        // 34824
#define SMF (OWC + 256 * NSTC)        // 54280 floats
#define SMB (SMF * 4)                 // 217120 bytes

__device__ __forceinline__ float sigmoid_f(float z) {
    return 1.0f / (1.0f + __expf(-z));
}
__device__ __forceinline__ float tanh_f(float z) {
    return fmaf(2.0f, sigmoid_f(2.0f * z), -1.0f);
}

__global__ __launch_bounds__(256, 1) __cluster_dims__(4, 1, 1)
void gru_scan8(const float* __restrict__ wuc,
               const float* __restrict__ wrc,
               const float* __restrict__ wcc,
               const float* __restrict__ bu,
               const float* __restrict__ br,
               const float* __restrict__ bc,
               const float* __restrict__ a0,
               float* __restrict__ out)
{
    extern __shared__ float sm[];
    float* wu_s = sm + OWU;
    float* wr_s = sm + OWR;
    float* wc_s = sm + OWC;

    const int tid = threadIdx.x;
    const uint32_t rank = ctarank();
    const int n0 = (int)rank * 64;
    const int r0 = (blockIdx.x >> 2) * 8;

    const int ks    = tid & 15;
    const int ng    = tid >> 4;
    const int nbase = ng * 4;
    const bool b3 = (ks & 8) != 0, b2 = (ks & 4) != 0,
               b1 = (ks & 2) != 0, b0 = (ks & 1) != 0;
    const int p     = ks & 3;
    const int col_g = n0 + nbase + (ks >> 2);
    const int m_own = r0 + 2 * p;
    const int jloc  = (int)rank * 4;

    const uint32_t barH = smem_u32(sm);
    const uint32_t barC = barH + 8;
    if (tid == 0) { mbar_init(barH, 4); mbar_init(barC, 4); }

    // ---- weights k-major into smem (each word written once) ----
    for (int i = tid; i < 64 * 256; i += 256) {
        int k = i >> 6, n = i & 63;
        wu_s[k * NSTW + n] = wuc[k * UDIM + n0 + n];
        wr_s[k * NSTW + n] = wrc[k * UDIM + n0 + n];
        wc_s[k * NSTC + n] = wcc[k * UDIM + n0 + n];
    }
    // ---- c init into wc pads: c[u][r] at wc_s[u*76 + 64 + r] ----
    for (int i = tid; i < 256 * 8; i += 256) {
        int u = i >> 3, r = i & 7;
        wc_s[u * NSTC + 64 + r] = a0[(size_t)(r0 + r) * UDIM + u];
    }
    float cme0 = a0[(size_t)(m_own + 0) * UDIM + col_g];
    float cme1 = a0[(size_t)(m_own + 1) * UDIM + col_g];
    const float bun = bu[col_g], brn = br[col_g], bcn = bc[col_g];

    uint32_t hbase = (p < 2)
        ? smem_u32(wu_s + col_g * NSTW + 64 + 2 * p)
        : smem_u32(wr_s + col_g * NSTW + 64 + 2 * (p - 2));
    uint32_t cbase = smem_u32(wc_s + col_g * NSTC + 64 + 2 * p);
    uint32_t hdst[4], cdst[4];
    #pragma unroll
    for (int d = 0; d < 4; d++) {
        hdst[d] = mapa_rank(hbase, d);
        cdst[d] = mapa_rank(cbase, d);
    }

    __syncthreads();
    CLUSTER_SYNC_();

    // Allow the dependent xproj grid to start co-scheduling now.
    cudaTriggerProgrammaticLaunchCompletion();

    const float* __restrict__ xu = g_xp;
    const float* __restrict__ xr = g_xp + XP_STRIDE;
    const float* __restrict__ xc = g_xp + 2ULL * XP_STRIDE;

    const float* wup = wu_s + ks * NSTW + nbase;
    const float* wrp = wr_s + ks * NSTW + nbase;
    const float* wcp = wc_s + ks * NSTC + nbase;
    const float* cpp = wc_s + ks * NSTC + 64;
    const float* hup = wu_s + ks * NSTW + 64;
    const float* hrp = wr_s + ks * NSTW + 64;

    unsigned long long aU[16], aR[16], aC[16];

    // producer must have finished t=0 before the first x loads
    wait_ready(0);

    for (int t = 0; t < TDIM; t++) {
        const uint32_t ph = (uint32_t)(t & 1);

        const size_t xo = (size_t)t * (MDIM * UDIM) + (size_t)m_own * UDIM + col_g;
        const float xu0 = __ldg(xu + xo), xu1 = __ldg(xu + xo + UDIM);
        const float xr0 = __ldg(xr + xo), xr1 = __ldg(xr + xo + UDIM);
        const float xc0 = __ldg(xc + xo), xc1 = __ldg(xc + xo + UDIM);

        // ================= phase A: pre_u, pre_r =================
        #pragma unroll
        for (int i = 0; i < 16; i++) { aU[i] = 0ULL; aR[i] = 0ULL; }

        auto bodyA = [&](int j) {
            const float4 wu4 = *(const float4*)(wup + j * (16 * NSTW));
            const float4 wr4 = *(const float4*)(wrp + j * (16 * NSTW));
            const ulonglong2 cA = *(const ulonglong2*)(cpp + j * (16 * NSTC));
            const ulonglong2 cB = *(const ulonglong2*)(cpp + j * (16 * NSTC) + 4);
            const unsigned long long c2[4] = {cA.x, cA.y, cB.x, cB.y};
            const float wuf[4] = {wu4.x, wu4.y, wu4.z, wu4.w};
            const float wrf[4] = {wr4.x, wr4.y, wr4.z, wr4.w};
            #pragma unroll
            for (int c = 0; c < 4; c++) {
                const unsigned long long du = dup2(wuf[c]);
                const unsigned long long dr = dup2(wrf[c]);
                #pragma unroll
                for (int q = 0; q < 4; q++) {
                    FFMA2(aU[c * 4 + q], c2[q], du);
                    FFMA2(aR[c * 4 + q], c2[q], dr);
                }
            }
        };

        #pragma unroll
        for (int jj = 0; jj < 4; jj++) bodyA(jloc + jj);
        if (t > 0) mbar_wait_parity(barC, (uint32_t)((t - 1) & 1));
        #pragma unroll
        for (int g = 1; g < 4; g++) {
            const int jb = (((int)rank + g) & 3) * 4;
            #pragma unroll
            for (int jj = 0; jj < 4; jj++) bodyA(jb + jj);
        }

        redstep<8>(aU, b3, 8);  redstep<8>(aR, b3, 8);
        redstep<4>(aU, b2, 4);  redstep<4>(aR, b2, 4);
        redstep<2>(aU, b1, 2);  redstep<2>(aR, b1, 2);
        redstep<1>(aU, b0, 1);  redstep<1>(aR, b0, 1);

        float pu0, pu1, pr0, pr1;
        unpack2(pu0, pu1, aU[0]);
        unpack2(pr0, pr1, aR[0]);

        const float h0 = sigmoid_f(pr0 + xr0 + brn) * cme0;
        const float h1 = sigmoid_f(pr1 + xr1 + brn) * cme1;
        {
            const unsigned long long h01 = pack2(h0, h1);
            #pragma unroll
            for (int d = 0; d < 4; d++) st_cluster_u64(hdst[d], h01);
        }
        const float gu0 = sigmoid_f(pu0 + xu0 + bun);
        const float gu1 = sigmoid_f(pu1 + xu1 + bun);

        // Poll for next step's x-projections in the A->B slack window.
        if (t + 1 < TDIM) wait_ready(t + 1);

        __syncthreads();                       // local h visible CTA-wide
        if (tid < 4) mbar_arrive_rank(barH, (uint32_t)tid);

        // ================= phase B: pre_c =================
        #pragma unroll
        for (int i = 0; i < 16; i++) aC[i] = 0ULL;

        auto bodyB = [&](int j) {
            const float4 wc4 = *(const float4*)(wcp + j * (16 * NSTC));
            const ulonglong2 hA = *(const ulonglong2*)(hup + j * (16 * NSTW));
            const ulonglong2 hB = *(const ulonglong2*)(hrp + j * (16 * NSTW));
            const unsigned long long h2[4] = {hA.x, hA.y, hB.x, hB.y};
            const float wcf[4] = {wc4.x, wc4.y, wc4.z, wc4.w};
            #pragma unroll
            for (int c = 0; c < 4; c++) {
                const unsigned long long dc = dup2(wcf[c]);
                #pragma unroll
                for (int q = 0; q < 4; q++)
                    FFMA2(aC[c * 4 + q], h2[q], dc);
            }
        };

        #pragma unroll
        for (int jj = 0; jj < 4; jj++) bodyB(jloc + jj);
        mbar_wait_parity(barH, ph);
        #pragma unroll
        for (int g = 1; g < 4; g++) {
            const int jb = (((int)rank + g) & 3) * 4;
            #pragma unroll
            for (int jj = 0; jj < 4; jj++) bodyB(jb + jj);
        }

        redstep<8>(aC, b3, 8);
        redstep<4>(aC, b2, 4);
        redstep<2>(aC, b1, 2);
        redstep<1>(aC, b0, 1);

        float pc0, pc1;
        unpack2(pc0, pc1, aC[0]);

        const float cand0 = tanh_f(pc0 + xc0 + bcn);
        const float cand1 = tanh_f(pc1 + xc1 + bcn);
        cme0 = fmaf(gu0, cand0 - cme0, cme0);
        cme1 = fmaf(gu1, cand1 - cme1, cme1);

        {
            const unsigned long long c01 = pack2(cme0, cme1);
            #pragma unroll
            for (int d = 0; d < 4; d++) st_cluster_u64(cdst[d], c01);
        }
        __syncthreads();                       // local c visible CTA-wide
        if (tid < 4) mbar_arrive_rank(barC, (uint32_t)tid);
    }

    out[(size_t)(m_own + 0) * UDIM + col_g] = cme0;
    out[(size_t)(m_own + 1) * UDIM + col_g] = cme1;

    CLUSTER_SYNC_();   // no CTA exits while peers' DSMEM stores in flight
}

// =====================================================================
// Launch: memset(cnt) -> scan (primary, triggers) -> xproj (secondary,
// ProgrammaticStreamSerialization) so the producer co-schedules with
// the consumer and the x-projection GEMM hides inside the scan's idle
// fma slots.
// Inputs (metadata order):
//  0:x [256,512,256]  1:a0 [256,256]
//  2:wcx 3:wcc 4:bc   5:wux 6:wuc 7:bu   8:wrx 9:wrc 10:br
// =====================================================================
extern "C" void kernel_launch(void* const* d_in, const int* in_sizes, int n_in,
                              void* d_out, int out_size)
{
    const float* x   = (const float*)d_in[0];
    const float* a0  = (const float*)d_in[1];
    const float* wcx = (const float*)d_in[2];
    const float* wcc = (const float*)d_in[3];
    const float* bc  = (const float*)d_in[4];
    const float* wux = (const float*)d_in[5];
    const float* wuc = (const float*)d_in[6];
    const float* bu  = (const float*)d_in[7];
    const float* wrx = (const float*)d_in[8];
    const float* wrc = (const float*)d_in[9];
    const float* br  = (const float*)d_in[10];
    float* out = (float*)d_out;

    // Reset per-step counters (graph-capturable async memset, no alloc).
    void* cnt_ptr = nullptr;
    cudaGetSymbolAddress(&cnt_ptr, g_cnt);
    cudaMemsetAsync(cnt_ptr, 0, TDIM * sizeof(int));

    cudaFuncSetAttribute(gru_scan8,
                         cudaFuncAttributeMaxDynamicSharedMemorySize, SMB);

    // Primary: the scan (cluster dims are compile-time via __cluster_dims__).
    gru_scan8<<<128, 256, SMB>>>(wuc, wrc, wcc, bu, br, bc, a0, out);

    // Secondary: xproj with programmatic stream serialization — its CTAs
    // may launch as soon as all scan CTAs call the trigger, filling the
    // per-SM resources the scan leaves free (6.3KB smem, 128 thr, <=128 regs).
    cudaLaunchConfig_t cfg = {};
    cfg.gridDim  = dim3((MDIM * TDIM) / 64, UDIM / 128, 3);
    cfg.blockDim = dim3(128, 1, 1);
    cfg.dynamicSmemBytes = 0;
    cfg.stream = 0;
    cudaLaunchAttribute attrs[1];
    attrs[0].id = cudaLaunchAttributeProgrammaticStreamSerialization;
    attrs[0].val.programmaticStreamSerializationAllowed = 1;
    cfg.attrs = attrs;
    cfg.numAttrs = 1;
    cudaLaunchKernelEx(&cfg, xproj_kernel, x, wux, wrx, wcx);
}